// round 1
// baseline (speedup 1.0000x reference)
#include <cuda_runtime.h>
#include <math.h>

#define BATCH 64
#define NOBJ  16
#define NCLS  7
#define HWDIM 108
#define H1    52
#define OC1   32
#define H2    24
#define OC2   64
#define NFC   36864      // OC2 * H2 * H2
#define NJ    512
#define NSPLIT 16
#define CHUNK  2304      // NFC / NSPLIT (= 4 channels of 576)
#define EPSV  1e-5f

// ---------------- scratch (device globals; no allocation) ----------------
__device__ float g_layout[BATCH * NCLS * HWDIM * HWDIM];   // ~20.9 MB
__device__ float g_conv1 [BATCH * OC1 * H1 * H1];          // ~22.2 MB
__device__ float g_conv2 [BATCH * OC2 * H2 * H2];          // ~9.4 MB
__device__ float g_part  [NSPLIT * BATCH * NJ];            // 2 MB
__device__ float g_ybuf  [BATCH * NJ];
__device__ float g_sums1[OC1], g_ss1[OC1];
__device__ float g_sums2[OC2], g_ss2[OC2];

// ---------------- K1: layout_bbox + transpose to NCHW ----------------
__global__ void k_layout(const float* __restrict__ image) {
    __shared__ float sx1[NOBJ], sx2[NOBJ], sy1[NOBJ], sy2[NOBJ];
    __shared__ float scls[NOBJ][NCLS];
    const int b = blockIdx.y;
    const int t = threadIdx.x;
    if (t < NOBJ) {
        const float* p = image + (b * NOBJ + t) * (4 + NCLS);
        float xc = p[0] * 108.f, yc = p[1] * 108.f;
        float w  = p[2] * 108.f, h  = p[3] * 108.f;
        sx1[t] = xc - 0.5f * w; sx2[t] = xc + 0.5f * w;
        sy1[t] = yc - 0.5f * h; sy2[t] = yc + 0.5f * h;
        #pragma unroll
        for (int c = 0; c < NCLS; c++) scls[t][c] = p[4 + c];
    }
    __syncthreads();
    const int pix = blockIdx.x * 256 + t;
    if (pix >= HWDIM * HWDIM) return;
    const int hh = pix / HWDIM, ww = pix % HWDIM;
    const float yt = (float)hh, xt = (float)ww;
    float acc[NCLS];
    #pragma unroll
    for (int c = 0; c < NCLS; c++) acc[c] = -1e30f;
    for (int o = 0; o < NOBJ; o++) {
        float x1d = xt - sx1[o], x2d = sx2[o] - xt;
        float y1d = yt - sy1[o], y2d = sy2[o] - yt;
        float yband = fminf(fmaxf(y1d, 0.f), 1.f) * fminf(fmaxf(y2d, 0.f), 1.f);
        float xband = fminf(fmaxf(x1d, 0.f), 1.f) * fminf(fmaxf(x2d, 0.f), 1.f);
        float l1 = fmaxf(1.f - fabsf(x1d), 0.f) * yband;
        float l2 = fmaxf(1.f - fabsf(x2d), 0.f) * yband;
        float l3 = fmaxf(1.f - fabsf(y1d), 0.f) * xband;
        float l4 = fmaxf(1.f - fabsf(y2d), 0.f) * xband;
        float m = fmaxf(fmaxf(l1, l2), fmaxf(l3, l4));
        #pragma unroll
        for (int c = 0; c < NCLS; c++) acc[c] = fmaxf(acc[c], m * scls[o][c]);
    }
    #pragma unroll
    for (int c = 0; c < NCLS; c++)
        g_layout[((b * NCLS + c) * HWDIM + hh) * HWDIM + ww] = acc[c];
}

// ---------------- K2: conv1 7->32, 5x5 stride 2 ----------------
// block: (xtile 0..3, ytile 0..6, b). out tile 16x8, all 32 oc.
// thread: 4 oc x 4 consecutive ow. 256 threads.
__global__ void k_conv1(const float* __restrict__ w, const float* __restrict__ bias) {
    __shared__ __align__(16) float xs[NCLS][19][36];
    __shared__ __align__(16) float ws[175][OC1];
    const int b   = blockIdx.z;
    const int oh0 = blockIdx.y * 8;
    const int ow0 = blockIdx.x * 16;
    const int t   = threadIdx.x;

    for (int i = t; i < NCLS * 19 * 36; i += 256) {
        int ic  = i / (19 * 36);
        int rem = i % (19 * 36);
        int r = rem / 36, cc = rem % 36;
        int row = 2 * oh0 + r, col = 2 * ow0 + cc;
        float v = 0.f;
        if (cc < 35 && row < HWDIM && col < HWDIM)
            v = g_layout[((b * NCLS + ic) * HWDIM + row) * HWDIM + col];
        xs[ic][r][cc] = v;
    }
    for (int i = t; i < 175 * OC1; i += 256) {
        int k = i / OC1, oc = i % OC1;
        ws[k][oc] = w[oc * 175 + k];
    }
    __syncthreads();

    const int oc0 = (t % 8) * 4;
    const int pg  = t / 8;
    const int r   = pg / 4;
    const int c0  = (pg % 4) * 4;

    float acc[4][4];
    #pragma unroll
    for (int q = 0; q < 4; q++)
        #pragma unroll
        for (int p = 0; p < 4; p++) acc[q][p] = 0.f;

    for (int ic = 0; ic < NCLS; ic++) {
        #pragma unroll
        for (int ky = 0; ky < 5; ky++) {
            const float* xrow = &xs[ic][2 * r + ky][2 * c0];
            float xr[11];
            #pragma unroll
            for (int u = 0; u < 11; u++) xr[u] = xrow[u];
            #pragma unroll
            for (int kx = 0; kx < 5; kx++) {
                float4 wv = *(const float4*)&ws[ic * 25 + ky * 5 + kx][oc0];
                #pragma unroll
                for (int p = 0; p < 4; p++) {
                    float xv = xr[2 * p + kx];
                    acc[0][p] += wv.x * xv;
                    acc[1][p] += wv.y * xv;
                    acc[2][p] += wv.z * xv;
                    acc[3][p] += wv.w * xv;
                }
            }
        }
    }
    const int oh = oh0 + r;
    if (oh < H1) {
        #pragma unroll
        for (int q = 0; q < 4; q++) {
            float bq = bias[oc0 + q];
            #pragma unroll
            for (int p = 0; p < 4; p++) {
                int ow = ow0 + c0 + p;
                if (ow < H1)
                    g_conv1[((b * OC1 + oc0 + q) * H1 + oh) * H1 + ow] = acc[q][p] + bq;
            }
        }
    }
}

// ---------------- K3/K5: deterministic per-channel sum/sumsq ----------------
__global__ void k_red1() {
    const int c = blockIdx.x, t = threadIdx.x;
    float s = 0.f, ss = 0.f;
    const int per = H1 * H1;
    for (int i = t; i < BATCH * per; i += 256) {
        int b = i / per, pos = i % per;
        float v = g_conv1[(b * OC1 + c) * per + pos];
        s += v; ss += v * v;
    }
    __shared__ float rs[256], rq[256];
    rs[t] = s; rq[t] = ss;
    __syncthreads();
    for (int off = 128; off > 0; off >>= 1) {
        if (t < off) { rs[t] += rs[t + off]; rq[t] += rq[t + off]; }
        __syncthreads();
    }
    if (t == 0) { g_sums1[c] = rs[0]; g_ss1[c] = rq[0]; }
}

__global__ void k_red2() {
    const int c = blockIdx.x, t = threadIdx.x;
    float s = 0.f, ss = 0.f;
    const int per = H2 * H2;
    for (int i = t; i < BATCH * per; i += 256) {
        int b = i / per, pos = i % per;
        float v = g_conv2[(b * OC2 + c) * per + pos];
        s += v; ss += v * v;
    }
    __shared__ float rs[256], rq[256];
    rs[t] = s; rq[t] = ss;
    __syncthreads();
    for (int off = 128; off > 0; off >>= 1) {
        if (t < off) { rs[t] += rs[t + off]; rq[t] += rq[t + off]; }
        __syncthreads();
    }
    if (t == 0) { g_sums2[c] = rs[0]; g_ss2[c] = rq[0]; }
}

// ---------------- K4: bn1+leaky fused into conv2 32->64, 5x5 stride 2 ----------------
// block: (xtile 0..2, ytile 0..2, b). out tile 8x8, all 64 oc. 4 ic staged at a time.
// thread: 4 oc x 4 consecutive ow. 256 threads.
__global__ void k_conv2(const float* __restrict__ w, const float* __restrict__ bias,
                        const float* __restrict__ g1, const float* __restrict__ b1) {
    __shared__ __align__(16) float xs[4][19][20];
    __shared__ __align__(16) float ws[4][25][OC2];
    __shared__ float sc1[OC1], sh1[OC1];
    const int b   = blockIdx.z;
    const int oh0 = blockIdx.y * 8;
    const int ow0 = blockIdx.x * 8;
    const int t   = threadIdx.x;

    if (t < OC1) {
        float n = (float)(BATCH * H1 * H1);
        float m = g_sums1[t] / n;
        float v = g_ss1[t] / n - m * m;
        float s = rsqrtf(v + EPSV) * g1[t];
        sc1[t] = s; sh1[t] = b1[t] - m * s;
    }
    __syncthreads();

    const int oc0 = (t % 16) * 4;
    const int pg  = t / 16;
    const int r   = pg / 2;
    const int c0  = (pg % 2) * 4;

    float acc[4][4];
    #pragma unroll
    for (int q = 0; q < 4; q++)
        #pragma unroll
        for (int p = 0; p < 4; p++) acc[q][p] = 0.f;

    for (int icb = 0; icb < OC1; icb += 4) {
        __syncthreads();
        for (int i = t; i < 4 * 19 * 20; i += 256) {
            int i2  = i / (19 * 20);
            int rem = i % (19 * 20);
            int rr = rem / 20, cc = rem % 20;
            float v = 0.f;
            if (cc < 19) {
                int ic = icb + i2;
                v = g_conv1[((b * OC1 + ic) * H1 + 2 * oh0 + rr) * H1 + 2 * ow0 + cc];
                v = v * sc1[ic] + sh1[ic];
                v = v > 0.f ? v : 0.2f * v;
            }
            xs[i2][rr][cc] = v;
        }
        for (int i = t; i < 4 * 25 * OC2; i += 256) {
            int i2  = i / (25 * OC2);
            int rem = i % (25 * OC2);
            int k = rem / OC2, oc = rem % OC2;
            ws[i2][k][oc] = w[(oc * OC1 + icb + i2) * 25 + k];
        }
        __syncthreads();

        #pragma unroll
        for (int i2 = 0; i2 < 4; i2++) {
            #pragma unroll
            for (int ky = 0; ky < 5; ky++) {
                const float* xrow = &xs[i2][2 * r + ky][2 * c0];
                float xr[11];
                #pragma unroll
                for (int u = 0; u < 11; u++) xr[u] = xrow[u];
                #pragma unroll
                for (int kx = 0; kx < 5; kx++) {
                    float4 wv = *(const float4*)&ws[i2][ky * 5 + kx][oc0];
                    #pragma unroll
                    for (int p = 0; p < 4; p++) {
                        float xv = xr[2 * p + kx];
                        acc[0][p] += wv.x * xv;
                        acc[1][p] += wv.y * xv;
                        acc[2][p] += wv.z * xv;
                        acc[3][p] += wv.w * xv;
                    }
                }
            }
        }
    }
    const int oh = oh0 + r;
    #pragma unroll
    for (int q = 0; q < 4; q++) {
        float bq = bias[oc0 + q];
        #pragma unroll
        for (int p = 0; p < 4; p++) {
            int ow = ow0 + c0 + p;
            g_conv2[((b * OC2 + oc0 + q) * H2 + oh) * H2 + ow] = acc[q][p] + bq;
        }
    }
}

// ---------------- K6: fc1 GEMM (bn2+leaky fused on X load), split-K partials ----------------
// block: (jb 0..15, sp 0..15). 32 j's x 64 b per block; K chunk = 64.
// thread: 4j x 2b. 256 threads.
__global__ void k_fc1(const float* __restrict__ w,
                      const float* __restrict__ g2, const float* __restrict__ b2) {
    __shared__ __align__(16) float Xs[BATCH][68];   // [b][kk]
    __shared__ __align__(16) float Ws[64][36];      // [kk][jj], padded
    __shared__ float sc2[OC2], sh2[OC2];
    const int jb = blockIdx.x, sp = blockIdx.y;
    const int t = threadIdx.x;

    if (t < OC2) {
        float n = (float)(BATCH * H2 * H2);
        float m = g_sums2[t] / n;
        float v = g_ss2[t] / n - m * m;
        float s = rsqrtf(v + EPSV) * g2[t];
        sc2[t] = s; sh2[t] = b2[t] - m * s;
    }
    __syncthreads();

    const int j0 = (t % 8) * 4;
    const int b0 = (t / 8) * 2;
    float acc[4][2];
    #pragma unroll
    for (int q = 0; q < 4; q++) { acc[q][0] = 0.f; acc[q][1] = 0.f; }

    const int base = sp * CHUNK;
    for (int ch = 0; ch < CHUNK / 64; ch++) {
        const int k0 = base + ch * 64;
        const int c = k0 / (H2 * H2);   // 64-chunks never cross a 576 channel boundary
        const float sc = sc2[c], sh = sh2[c];
        __syncthreads();
        #pragma unroll
        for (int rep = 0; rep < 8; rep++) {
            int idx = rep * 256 + t;
            int kk = idx & 63, jj = idx >> 6;
            Ws[kk][jj] = w[(jb * 32 + jj) * NFC + k0 + kk];
        }
        #pragma unroll
        for (int rep = 0; rep < 16; rep++) {
            int idx = rep * 256 + t;
            int kk = idx & 63, bb = idx >> 6;
            float v = g_conv2[bb * NFC + k0 + kk];
            v = v * sc + sh;
            v = v > 0.f ? v : 0.2f * v;
            Xs[bb][kk] = v;
        }
        __syncthreads();
        #pragma unroll 4
        for (int kk = 0; kk < 64; kk++) {
            float4 wv = *(const float4*)&Ws[kk][j0];
            float x0 = Xs[b0][kk];
            float x1 = Xs[b0 + 1][kk];
            acc[0][0] += wv.x * x0; acc[0][1] += wv.x * x1;
            acc[1][0] += wv.y * x0; acc[1][1] += wv.y * x1;
            acc[2][0] += wv.z * x0; acc[2][1] += wv.z * x1;
            acc[3][0] += wv.w * x0; acc[3][1] += wv.w * x1;
        }
    }
    #pragma unroll
    for (int p = 0; p < 2; p++)
        #pragma unroll
        for (int q = 0; q < 4; q++)
            g_part[(sp * BATCH + b0 + p) * NJ + jb * 32 + j0 + q] = acc[q][p];
}

// ---------------- K7: reduce split-K partials + fc1 bias ----------------
__global__ void k_redpart(const float* __restrict__ fc1b) {
    const int b = blockIdx.x, j = threadIdx.x;
    float y = fc1b[j];
    #pragma unroll
    for (int s = 0; s < NSPLIT; s++) y += g_part[(s * BATCH + b) * NJ + j];
    g_ybuf[b * NJ + j] = y;
}

// ---------------- K8: bn3 + leaky + fc2 + sigmoid ----------------
__global__ void k_final(const float* __restrict__ g3, const float* __restrict__ b3,
                        const float* __restrict__ w2, const float* __restrict__ bias2,
                        float* __restrict__ out) {
    __shared__ float sc[NJ], sh[NJ], w2s[NJ];
    const int t = threadIdx.x;
    float s = 0.f, ss = 0.f;
    for (int b = 0; b < BATCH; b++) {
        float v = g_ybuf[b * NJ + t];
        s += v; ss += v * v;
    }
    float m = s * (1.f / BATCH);
    float var = ss * (1.f / BATCH) - m * m;
    float scale = rsqrtf(var + EPSV) * g3[t];
    sc[t] = scale; sh[t] = b3[t] - m * scale; w2s[t] = w2[t];
    __syncthreads();
    const int warp = t / 32, lane = t % 32;
    for (int b = warp * 4; b < warp * 4 + 4; b++) {
        float p = 0.f;
        for (int j = lane; j < NJ; j += 32) {
            float v = g_ybuf[b * NJ + j] * sc[j] + sh[j];
            v = v > 0.f ? v : 0.2f * v;
            p += v * w2s[j];
        }
        #pragma unroll
        for (int off = 16; off > 0; off >>= 1)
            p += __shfl_down_sync(0xffffffffu, p, off);
        if (lane == 0) out[b] = 1.f / (1.f + expf(-(p + bias2[0])));
    }
}

// ---------------- launch ----------------
extern "C" void kernel_launch(void* const* d_in, const int* in_sizes, int n_in,
                              void* d_out, int out_size) {
    (void)in_sizes; (void)n_in; (void)out_size;
    const float* image = (const float*)d_in[0];
    const float* c1w = (const float*)d_in[1];
    const float* c1b = (const float*)d_in[2];
    const float* g1  = (const float*)d_in[3];
    const float* b1  = (const float*)d_in[4];
    const float* c2w = (const float*)d_in[5];
    const float* c2b = (const float*)d_in[6];
    const float* g2  = (const float*)d_in[7];
    const float* b2  = (const float*)d_in[8];
    const float* fw1 = (const float*)d_in[9];
    const float* fb1 = (const float*)d_in[10];
    const float* g3  = (const float*)d_in[11];
    const float* b3  = (const float*)d_in[12];
    const float* fw2 = (const float*)d_in[13];
    const float* fb2 = (const float*)d_in[14];
    float* out = (float*)d_out;

    k_layout <<<dim3(46, 64), 256>>>(image);
    k_conv1  <<<dim3(4, 7, 64), 256>>>(c1w, c1b);
    k_red1   <<<OC1, 256>>>();
    k_conv2  <<<dim3(3, 3, 64), 256>>>(c2w, c2b, g1, b1);
    k_red2   <<<OC2, 256>>>();
    k_fc1    <<<dim3(16, 16), 256>>>(fw1, g2, b2);
    k_redpart<<<BATCH, NJ>>>(fb1);
    k_final  <<<1, NJ>>>(g3, b3, fw2, fb2, out);
}

// round 2
// speedup vs baseline: 1.2903x; 1.2903x over previous
#include <cuda_runtime.h>
#include <math.h>

#define BATCH 64
#define NOBJ  16
#define NCLS  7
#define HWDIM 108
#define H1    52
#define OC1   32
#define H2    24
#define OC2   64
#define NFC   36864      // OC2 * H2 * H2
#define NJ    512
#define NSPLIT 32
#define CHUNK  1152      // NFC / NSPLIT (= 2 channels of 576)
#define EPSV  1e-5f

typedef unsigned long long u64;

__device__ __forceinline__ void fma2(u64& d, u64 a, u64 b) {
    asm("fma.rn.f32x2 %0, %1, %2, %0;" : "+l"(d) : "l"(a), "l"(b));
}
__device__ __forceinline__ float2 unpk(u64 v) {
    float2 r; asm("mov.b64 {%0, %1}, %2;" : "=f"(r.x), "=f"(r.y) : "l"(v)); return r;
}

// ---------------- scratch (device globals; no allocation) ----------------
__device__ float g_layout[BATCH * NCLS * HWDIM * HWDIM];
__device__ float g_conv1 [BATCH * OC1 * H1 * H1];
__device__ float g_conv2 [BATCH * OC2 * H2 * H2];
__device__ float g_part  [NSPLIT * BATCH * NJ];
__device__ float g_ybuf  [BATCH * NJ];
__device__ float g_s1p[8][OC1], g_q1p[8][OC1];
__device__ float g_s2p[8][OC2], g_q2p[8][OC2];
__device__ float g_w1t[NCLS * 25 * OC1];   // [ic*25+k][oc]
__device__ float g_w2t[OC1 * 25 * OC2];    // [ic*25+k][oc]

// ---------------- weight transpose prep ----------------
__global__ void k_wt1(const float* __restrict__ w) {
    int i = blockIdx.x * 256 + threadIdx.x;
    if (i < NCLS * 25 * OC1) {
        int kic = i / OC1, oc = i % OC1;
        g_w1t[i] = w[oc * 175 + kic];
    }
}
__global__ void k_wt2(const float* __restrict__ w) {
    int i = blockIdx.x * 256 + threadIdx.x;
    if (i < OC1 * 25 * OC2) {
        int kic = i / OC2, oc = i % OC2;
        g_w2t[i] = w[oc * 800 + kic];
    }
}

// ---------------- K1: layout_bbox + transpose to NCHW ----------------
__global__ void k_layout(const float* __restrict__ image) {
    __shared__ float sx1[NOBJ], sx2[NOBJ], sy1[NOBJ], sy2[NOBJ];
    __shared__ float scls[NOBJ][NCLS];
    const int b = blockIdx.y;
    const int t = threadIdx.x;
    if (t < NOBJ) {
        const float* p = image + (b * NOBJ + t) * (4 + NCLS);
        float xc = p[0] * 108.f, yc = p[1] * 108.f;
        float w  = p[2] * 108.f, h  = p[3] * 108.f;
        sx1[t] = xc - 0.5f * w; sx2[t] = xc + 0.5f * w;
        sy1[t] = yc - 0.5f * h; sy2[t] = yc + 0.5f * h;
        #pragma unroll
        for (int c = 0; c < NCLS; c++) scls[t][c] = p[4 + c];
    }
    __syncthreads();
    const int pix = blockIdx.x * 256 + t;
    if (pix >= HWDIM * HWDIM) return;
    const int hh = pix / HWDIM, ww = pix % HWDIM;
    const float yt = (float)hh, xt = (float)ww;
    float acc[NCLS];
    #pragma unroll
    for (int c = 0; c < NCLS; c++) acc[c] = -1e30f;
    for (int o = 0; o < NOBJ; o++) {
        float x1d = xt - sx1[o], x2d = sx2[o] - xt;
        float y1d = yt - sy1[o], y2d = sy2[o] - yt;
        float yband = fminf(fmaxf(y1d, 0.f), 1.f) * fminf(fmaxf(y2d, 0.f), 1.f);
        float xband = fminf(fmaxf(x1d, 0.f), 1.f) * fminf(fmaxf(x2d, 0.f), 1.f);
        float l1 = fmaxf(1.f - fabsf(x1d), 0.f) * yband;
        float l2 = fmaxf(1.f - fabsf(x2d), 0.f) * yband;
        float l3 = fmaxf(1.f - fabsf(y1d), 0.f) * xband;
        float l4 = fmaxf(1.f - fabsf(y2d), 0.f) * xband;
        float m = fmaxf(fmaxf(l1, l2), fmaxf(l3, l4));
        #pragma unroll
        for (int c = 0; c < NCLS; c++) acc[c] = fmaxf(acc[c], m * scls[o][c]);
    }
    #pragma unroll
    for (int c = 0; c < NCLS; c++)
        g_layout[((b * NCLS + c) * HWDIM + hh) * HWDIM + ww] = acc[c];
}

// ---------------- K2: conv1 7->32, 5x5 stride 2, f32x2 packed ----------------
// block: (xtile 0..6, ytile 0..6, b). out tile 8x8, 32 oc. 128 threads.
// thread: 4 oc (2 f32x2 pairs) x 4 consecutive ow, one row.
__global__ void __launch_bounds__(128) k_conv1(const float* __restrict__ bias) {
    __shared__ __align__(16) float xsd[NCLS][19][44];   // x duplicated {v,v}
    __shared__ __align__(16) float ws[175 * OC1];       // [kic][oc]
    const int b   = blockIdx.z;
    const int oh0 = blockIdx.y * 8;
    const int ow0 = blockIdx.x * 8;
    const int t   = threadIdx.x;

    for (int i = t; i < NCLS * 19 * 19; i += 128) {
        int ic  = i / 361;
        int rem = i % 361;
        int rr = rem / 19, cc = rem % 19;
        int row = 2 * oh0 + rr, col = 2 * ow0 + cc;
        float v = 0.f;
        if (row < HWDIM && col < HWDIM)
            v = g_layout[((b * NCLS + ic) * HWDIM + row) * HWDIM + col];
        *(float2*)&xsd[ic][rr][2 * cc] = make_float2(v, v);
    }
    for (int i = t; i < 175 * OC1 / 4; i += 128)
        ((float4*)ws)[i] = ((const float4*)g_w1t)[i];
    __syncthreads();

    const int oc0 = (t & 7) * 4;
    const int pg  = t >> 3;          // 0..15
    const int r   = pg >> 1;         // 0..7
    const int c0  = (pg & 1) * 4;    // 0 or 4

    u64 acc[2][4];
    #pragma unroll
    for (int q = 0; q < 2; q++)
        #pragma unroll
        for (int p = 0; p < 4; p++) acc[q][p] = 0ull;

    for (int ic = 0; ic < NCLS; ic++) {
        #pragma unroll
        for (int ky = 0; ky < 5; ky++) {
            const float* xrow = &xsd[ic][2 * r + ky][4 * c0];
            u64 xd[11];
            #pragma unroll
            for (int u = 0; u < 11; u++) xd[u] = *(const u64*)(xrow + 2 * u);
            #pragma unroll
            for (int kx = 0; kx < 5; kx++) {
                ulonglong2 wq = *(const ulonglong2*)&ws[(ic * 25 + ky * 5 + kx) * OC1 + oc0];
                #pragma unroll
                for (int p = 0; p < 4; p++) {
                    fma2(acc[0][p], wq.x, xd[2 * p + kx]);
                    fma2(acc[1][p], wq.y, xd[2 * p + kx]);
                }
            }
        }
    }
    const int oh = oh0 + r;
    if (oh < H1) {
        #pragma unroll
        for (int q = 0; q < 2; q++) {
            float ba = bias[oc0 + 2 * q], bb = bias[oc0 + 2 * q + 1];
            #pragma unroll
            for (int p = 0; p < 4; p++) {
                int ow = ow0 + c0 + p;
                if (ow < H1) {
                    float2 v = unpk(acc[q][p]);
                    g_conv1[((b * OC1 + oc0 + 2 * q)     * H1 + oh) * H1 + ow] = v.x + ba;
                    g_conv1[((b * OC1 + oc0 + 2 * q + 1) * H1 + oh) * H1 + ow] = v.y + bb;
                }
            }
        }
    }
}

// ---------------- K3/K5: two-stage deterministic per-channel sum/sumsq ----------------
__global__ void k_red1() {
    const int c = blockIdx.x, bg = blockIdx.y, t = threadIdx.x;
    float s = 0.f, ss = 0.f;
    for (int i = t; i < 8 * 676; i += 256) {
        int b = bg * 8 + i / 676;
        float4 v = *(const float4*)&g_conv1[(b * OC1 + c) * 2704 + (i % 676) * 4];
        s  += (v.x + v.y) + (v.z + v.w);
        ss += (v.x * v.x + v.y * v.y) + (v.z * v.z + v.w * v.w);
    }
    __shared__ float rs[256], rq[256];
    rs[t] = s; rq[t] = ss;
    __syncthreads();
    for (int off = 128; off > 0; off >>= 1) {
        if (t < off) { rs[t] += rs[t + off]; rq[t] += rq[t + off]; }
        __syncthreads();
    }
    if (t == 0) { g_s1p[bg][c] = rs[0]; g_q1p[bg][c] = rq[0]; }
}

__global__ void k_red2() {
    const int c = blockIdx.x, bg = blockIdx.y, t = threadIdx.x;
    float s = 0.f, ss = 0.f;
    for (int i = t; i < 8 * 144; i += 256) {
        int b = bg * 8 + i / 144;
        float4 v = *(const float4*)&g_conv2[(b * OC2 + c) * 576 + (i % 144) * 4];
        s  += (v.x + v.y) + (v.z + v.w);
        ss += (v.x * v.x + v.y * v.y) + (v.z * v.z + v.w * v.w);
    }
    __shared__ float rs[256], rq[256];
    rs[t] = s; rq[t] = ss;
    __syncthreads();
    for (int off = 128; off > 0; off >>= 1) {
        if (t < off) { rs[t] += rs[t + off]; rq[t] += rq[t + off]; }
        __syncthreads();
    }
    if (t == 0) { g_s2p[bg][c] = rs[0]; g_q2p[bg][c] = rq[0]; }
}

// ---------------- K4: bn1+leaky fused into conv2 32->64, f32x2 packed ----------------
// block: (xtile 0..2, ytile 0..2, b). out tile 8x8, 64 oc. 128 threads.
// thread: 4 oc (2 pairs) x 8 ow (full row).
__global__ void __launch_bounds__(128) k_conv2(const float* __restrict__ bias,
                        const float* __restrict__ g1, const float* __restrict__ b1) {
    __shared__ __align__(16) float xsd[4][19][40];
    __shared__ __align__(16) float ws[100 * OC2];
    __shared__ float sc1[OC1], sh1[OC1];
    const int b   = blockIdx.z;
    const int oh0 = blockIdx.y * 8;
    const int ow0 = blockIdx.x * 8;
    const int t   = threadIdx.x;

    if (t < OC1) {
        float s = 0.f, q = 0.f;
        #pragma unroll
        for (int i = 0; i < 8; i++) { s += g_s1p[i][t]; q += g_q1p[i][t]; }
        float n = (float)(BATCH * H1 * H1);
        float m = s / n;
        float v = q / n - m * m;
        float sc = rsqrtf(v + EPSV) * g1[t];
        sc1[t] = sc; sh1[t] = b1[t] - m * sc;
    }

    const int oc0 = (t & 15) * 4;
    const int r   = t >> 4;          // 0..7

    u64 acc[2][8];
    #pragma unroll
    for (int q = 0; q < 2; q++)
        #pragma unroll
        for (int p = 0; p < 8; p++) acc[q][p] = 0ull;

    for (int icb = 0; icb < OC1; icb += 4) {
        __syncthreads();
        for (int i = t; i < 4 * 19 * 19; i += 128) {
            int i2  = i / 361;
            int rem = i % 361;
            int rr = rem / 19, cc = rem % 19;
            int ic = icb + i2;
            float v = g_conv1[((b * OC1 + ic) * H1 + 2 * oh0 + rr) * H1 + 2 * ow0 + cc];
            v = v * sc1[ic] + sh1[ic];
            v = v > 0.f ? v : 0.2f * v;
            *(float2*)&xsd[i2][rr][2 * cc] = make_float2(v, v);
        }
        const float4* src = (const float4*)(g_w2t + icb * 25 * OC2);
        for (int i = t; i < 100 * OC2 / 4; i += 128)
            ((float4*)ws)[i] = src[i];
        __syncthreads();

        #pragma unroll
        for (int i2 = 0; i2 < 4; i2++) {
            #pragma unroll
            for (int ky = 0; ky < 5; ky++) {
                const float* xrow = xsd[i2][2 * r + ky];
                {   // positions 0..3 use x[0..10]
                    u64 xd[11];
                    #pragma unroll
                    for (int u = 0; u < 11; u++) xd[u] = *(const u64*)(xrow + 2 * u);
                    #pragma unroll
                    for (int kx = 0; kx < 5; kx++) {
                        ulonglong2 wq = *(const ulonglong2*)&ws[(i2 * 25 + ky * 5 + kx) * OC2 + oc0];
                        #pragma unroll
                        for (int p = 0; p < 4; p++) {
                            fma2(acc[0][p], wq.x, xd[2 * p + kx]);
                            fma2(acc[1][p], wq.y, xd[2 * p + kx]);
                        }
                    }
                }
                {   // positions 4..7 use x[8..18]
                    u64 xd[11];
                    #pragma unroll
                    for (int u = 0; u < 11; u++) xd[u] = *(const u64*)(xrow + 2 * (8 + u));
                    #pragma unroll
                    for (int kx = 0; kx < 5; kx++) {
                        ulonglong2 wq = *(const ulonglong2*)&ws[(i2 * 25 + ky * 5 + kx) * OC2 + oc0];
                        #pragma unroll
                        for (int p = 4; p < 8; p++) {
                            fma2(acc[0][p], wq.x, xd[2 * (p - 4) + kx]);
                            fma2(acc[1][p], wq.y, xd[2 * (p - 4) + kx]);
                        }
                    }
                }
            }
        }
    }
    const int oh = oh0 + r;
    #pragma unroll
    for (int q = 0; q < 2; q++) {
        float ba = bias[oc0 + 2 * q], bb = bias[oc0 + 2 * q + 1];
        #pragma unroll
        for (int p = 0; p < 8; p++) {
            int ow = ow0 + p;
            float2 v = unpk(acc[q][p]);
            g_conv2[((b * OC2 + oc0 + 2 * q)     * H2 + oh) * H2 + ow] = v.x + ba;
            g_conv2[((b * OC2 + oc0 + 2 * q + 1) * H2 + oh) * H2 + ow] = v.y + bb;
        }
    }
}

// ---------------- K6: fc1 GEMM (bn2+leaky fused), split-K, f32x2 packed ----------------
// block: (jb 0..15, sp 0..31). 32 j x 64 b; K chunk 64. 128 threads, thread 4j x 4b.
__global__ void __launch_bounds__(128) k_fc1(const float* __restrict__ w,
                      const float* __restrict__ g2, const float* __restrict__ b2) {
    __shared__ __align__(16) float Xsd[64][134];   // [kk][b duplicated]
    __shared__ __align__(16) float Ws[64][36];     // [kk][jj]
    __shared__ float sc2[OC2], sh2[OC2];
    const int jb = blockIdx.x, sp = blockIdx.y;
    const int t = threadIdx.x;

    if (t < OC2) {
        float s = 0.f, q = 0.f;
        #pragma unroll
        for (int i = 0; i < 8; i++) { s += g_s2p[i][t]; q += g_q2p[i][t]; }
        float n = (float)(BATCH * H2 * H2);
        float m = s / n;
        float v = q / n - m * m;
        float sc = rsqrtf(v + EPSV) * g2[t];
        sc2[t] = sc; sh2[t] = b2[t] - m * sc;
    }

    const int j0 = (t & 7) * 4;
    const int b0 = (t >> 3) * 4;
    u64 acc[2][4];
    #pragma unroll
    for (int q = 0; q < 2; q++)
        #pragma unroll
        for (int p = 0; p < 4; p++) acc[q][p] = 0ull;

    const int base = sp * CHUNK;
    for (int ch = 0; ch < CHUNK / 64; ch++) {
        const int k0 = base + ch * 64;
        const int c = k0 / 576;     // 64-blocks never cross a channel boundary
        __syncthreads();
        const float sc = sc2[c], sh = sh2[c];
        for (int i = t; i < 512; i += 128) {
            int jj = i >> 4, k4 = (i & 15) * 4;
            float4 v = *(const float4*)&w[(jb * 32 + jj) * NFC + k0 + k4];
            Ws[k4][jj] = v.x; Ws[k4 + 1][jj] = v.y; Ws[k4 + 2][jj] = v.z; Ws[k4 + 3][jj] = v.w;
        }
        for (int i = t; i < 1024; i += 128) {
            int bb = i >> 4, k4 = (i & 15) * 4;
            float4 v = *(const float4*)&g_conv2[bb * NFC + k0 + k4];
            float a0 = v.x * sc + sh; a0 = a0 > 0.f ? a0 : 0.2f * a0;
            float a1 = v.y * sc + sh; a1 = a1 > 0.f ? a1 : 0.2f * a1;
            float a2 = v.z * sc + sh; a2 = a2 > 0.f ? a2 : 0.2f * a2;
            float a3 = v.w * sc + sh; a3 = a3 > 0.f ? a3 : 0.2f * a3;
            *(float2*)&Xsd[k4][2 * bb]     = make_float2(a0, a0);
            *(float2*)&Xsd[k4 + 1][2 * bb] = make_float2(a1, a1);
            *(float2*)&Xsd[k4 + 2][2 * bb] = make_float2(a2, a2);
            *(float2*)&Xsd[k4 + 3][2 * bb] = make_float2(a3, a3);
        }
        __syncthreads();
        #pragma unroll 8
        for (int kk = 0; kk < 64; kk++) {
            ulonglong2 wq = *(const ulonglong2*)&Ws[kk][j0];
            #pragma unroll
            for (int p = 0; p < 4; p++) {
                u64 xv = *(const u64*)&Xsd[kk][2 * (b0 + p)];
                fma2(acc[0][p], wq.x, xv);
                fma2(acc[1][p], wq.y, xv);
            }
        }
    }
    #pragma unroll
    for (int p = 0; p < 4; p++) {
        float2 v0 = unpk(acc[0][p]), v1 = unpk(acc[1][p]);
        float* dst = &g_part[(sp * BATCH + b0 + p) * NJ + jb * 32 + j0];
        dst[0] = v0.x; dst[1] = v0.y; dst[2] = v1.x; dst[3] = v1.y;
    }
}

// ---------------- K7: reduce split-K partials + fc1 bias ----------------
__global__ void k_redpart(const float* __restrict__ fc1b) {
    const int b = blockIdx.x, j = threadIdx.x;
    float y = fc1b[j];
    #pragma unroll
    for (int s = 0; s < NSPLIT; s++) y += g_part[(s * BATCH + b) * NJ + j];
    g_ybuf[b * NJ + j] = y;
}

// ---------------- K8: bn3 + leaky + fc2 + sigmoid ----------------
__global__ void k_final(const float* __restrict__ g3, const float* __restrict__ b3,
                        const float* __restrict__ w2, const float* __restrict__ bias2,
                        float* __restrict__ out) {
    __shared__ float sc[NJ], sh[NJ], w2s[NJ];
    const int t = threadIdx.x;
    float s = 0.f, ss = 0.f;
    for (int b = 0; b < BATCH; b++) {
        float v = g_ybuf[b * NJ + t];
        s += v; ss += v * v;
    }
    float m = s * (1.f / BATCH);
    float var = ss * (1.f / BATCH) - m * m;
    float scale = rsqrtf(var + EPSV) * g3[t];
    sc[t] = scale; sh[t] = b3[t] - m * scale; w2s[t] = w2[t];
    __syncthreads();
    const int warp = t / 32, lane = t % 32;
    for (int b = warp * 4; b < warp * 4 + 4; b++) {
        float p = 0.f;
        for (int j = lane; j < NJ; j += 32) {
            float v = g_ybuf[b * NJ + j] * sc[j] + sh[j];
            v = v > 0.f ? v : 0.2f * v;
            p += v * w2s[j];
        }
        #pragma unroll
        for (int off = 16; off > 0; off >>= 1)
            p += __shfl_down_sync(0xffffffffu, p, off);
        if (lane == 0) out[b] = 1.f / (1.f + expf(-(p + bias2[0])));
    }
}

// ---------------- launch ----------------
extern "C" void kernel_launch(void* const* d_in, const int* in_sizes, int n_in,
                              void* d_out, int out_size) {
    (void)in_sizes; (void)n_in; (void)out_size;
    const float* image = (const float*)d_in[0];
    const float* c1w = (const float*)d_in[1];
    const float* c1b = (const float*)d_in[2];
    const float* g1  = (const float*)d_in[3];
    const float* b1  = (const float*)d_in[4];
    const float* c2w = (const float*)d_in[5];
    const float* c2b = (const float*)d_in[6];
    const float* g2  = (const float*)d_in[7];
    const float* b2  = (const float*)d_in[8];
    const float* fw1 = (const float*)d_in[9];
    const float* fb1 = (const float*)d_in[10];
    const float* g3  = (const float*)d_in[11];
    const float* b3  = (const float*)d_in[12];
    const float* fw2 = (const float*)d_in[13];
    const float* fb2 = (const float*)d_in[14];
    float* out = (float*)d_out;

    k_wt1    <<<22, 256>>>(c1w);
    k_wt2    <<<200, 256>>>(c2w);
    k_layout <<<dim3(46, 64), 256>>>(image);
    k_conv1  <<<dim3(7, 7, 64), 128>>>(c1b);
    k_red1   <<<dim3(OC1, 8), 256>>>();
    k_conv2  <<<dim3(3, 3, 64), 128>>>(c2b, g1, b1);
    k_red2   <<<dim3(OC2, 8), 256>>>();
    k_fc1    <<<dim3(16, NSPLIT), 128>>>(fw1, g2, b2);
    k_redpart<<<BATCH, NJ>>>(fb1);
    k_final  <<<1, NJ>>>(g3, b3, fw2, fb2, out);
}